// round 14
// baseline (speedup 1.0000x reference)
#include <cuda_runtime.h>
#include <cuda_bf16.h>

#define NMAX 16384
#define FDIM 32
#define KDIM 16
#define EMAX 262144

// Scratch (no allocations allowed) — sizes fixed by the problem setup.
__device__ __align__(16) float g_x0[NMAX * FDIM];
__device__ __align__(16) float g_y[NMAX * FDIM];
__device__ float g_epair[NMAX];
__device__ __align__(16) float g_Wc[KDIM * FDIM];
__device__ __align__(16) float4 g_rec[EMAX];   // compacted edges: (tt, cut, d|s<<14, z)
__device__ __align__(16) float4 g_pos4[NMAX];  // packed positions
__device__ float g_z23[32];                    // z^0.23 LUT
__device__ int g_cnt;

__device__ __forceinline__ void red4(float* addr, float a, float b, float c, float d) {
    atomicAdd(reinterpret_cast<float4*>(addr), make_float4(a, b, c, d));
}

// Zero accumulators + output + counter; build Wc + z^0.23 LUT; pack positions.
__global__ void init_kernel(float* __restrict__ out, int B,
                            const float* __restrict__ Wr10,
                            const float* __restrict__ Wr20,
                            const float* __restrict__ pos, int N) {
    int i = blockIdx.x * blockDim.x + threadIdx.x;
    int tot4 = N * FDIM / 4;
    float4 z4 = make_float4(0.f, 0.f, 0.f, 0.f);
    if (i < tot4) {
        reinterpret_cast<float4*>(g_x0)[i] = z4;
        reinterpret_cast<float4*>(g_y)[i] = z4;
    }
    if (i < N) {
        g_epair[i] = 0.0f;
        g_pos4[i] = make_float4(pos[3 * i], pos[3 * i + 1], pos[3 * i + 2], 0.0f);
    }
    if (i < B) out[i] = 0.0f;
    if (i < KDIM * FDIM) g_Wc[i] = 0.282095f * Wr10[i] + Wr20[i];
    if (i < 32) g_z23[i] = powf((float)i, 0.23f);
    if (i == 0) g_cnt = 0;
}

// Scalar pass: one edge per lane. Distance, cutoff, tt, ZBL pair energy.
// Valid edges compacted into g_rec (block-aggregated atomic: 1 global RED/block).
__global__ void __launch_bounds__(256) scalar_kernel(
    const int*   __restrict__ dst,
    const int*   __restrict__ src,
    const int*   __restrict__ Z,
    int E) {
    __shared__ int sWarpCnt[8];
    __shared__ int sWarpOff[8];
    __shared__ int sBlockBase;

    int e = blockIdx.x * blockDim.x + threadIdx.x;
    int lane = threadIdx.x & 31;
    int wid = threadIdx.x >> 5;

    bool valid = false;
    float4 rec;
    if (e < E) {
        int d = __ldg(&dst[e]);
        int s = __ldg(&src[e]);
        float4 ps = __ldg(&g_pos4[s]);
        float4 pd = __ldg(&g_pos4[d]);
        float dx = ps.x - pd.x;
        float dy = ps.y - pd.y;
        float dz = ps.z - pd.z;
        float r = sqrtf(dx * dx + dy * dy + dz * dz + 1e-10f);
        r = fmaxf(r, 1e-4f);
        if (r < 6.0f) {
            valid = true;
            float u = r * (1.0f / 6.0f);
            float cut = __expf(-u * u / (1.0f - u * u));
            float tt = 2.0f * __expf(-r) - 1.0f;
            tt = fminf(fmaxf(tt, -1.0f), 1.0f);

            int zs = __ldg(&Z[s]);
            int zd = __ldg(&Z[d]);
            float zdf = (float)zd;
            float zsf = (float)zs;
            float aa = 0.46853332f / (__ldg(&g_z23[zd]) + __ldg(&g_z23[zs]) + 1e-10f);
            float ra = r / aa;
            float phi = 0.18175f * __expf(-3.1998f  * ra)
                      + 0.50986f * __expf(-0.94229f * ra)
                      + 0.28022f * __expf(-0.4029f  * ra)
                      + 0.02817f * __expf(-0.20162f * ra);
            float ep = 0.5f * 14.399645f * zdf * zsf / r * phi * cut;
            atomicAdd(&g_epair[d], ep);

            rec = make_float4(tt, cut,
                              __int_as_float(d | (s << 14)),
                              __int_as_float(zs));
        }
    }

    unsigned mask = __ballot_sync(0xffffffffu, valid);
    int wcnt = __popc(mask);
    if (lane == 0) sWarpCnt[wid] = wcnt;
    __syncthreads();
    if (threadIdx.x == 0) {
        int tot = 0;
#pragma unroll
        for (int w = 0; w < 8; w++) { sWarpOff[w] = tot; tot += sWarpCnt[w]; }
        sBlockBase = atomicAdd(&g_cnt, tot);
    }
    __syncthreads();
    if (valid) {
        int rank = __popc(mask & ((1u << lane) - 1u));
        g_rec[sBlockBase + sWarpOff[wid] + rank] = rec;
    }
}

// Feature pass over the compacted edge list. One octet of lanes per edge
// (4 channels/lane), 4 edges per warp-iteration, grid-stride over g_cnt.
// PASS=1: g_x0 += (rad@Wc)    * emb[Z[src]]
// PASS=2: g_y  += (rad@Wr1_1) * g_x0[src]
template <int PASS>
__global__ void __launch_bounds__(256) feat_kernel(
    const float* __restrict__ emb,    // PASS=1
    const float* __restrict__ Wext) { // Wr1_1 for PASS=2
    __shared__ float sW[KDIM * FDIM];
    if (PASS == 1) {
        for (int i = threadIdx.x; i < KDIM * FDIM; i += blockDim.x) sW[i] = g_Wc[i];
    } else {
        for (int i = threadIdx.x; i < KDIM * FDIM; i += blockDim.x) sW[i] = Wext[i];
    }
    __syncthreads();

    int cnt = g_cnt;
    int lane = threadIdx.x & 31;
    int oct = lane >> 3;
    int fg = (lane & 7) * 4;
    const float4* w4 = reinterpret_cast<const float4*>(&sW[fg]);  // row stride: 8 float4

    int warp_global = (blockIdx.x * blockDim.x + threadIdx.x) >> 5;
    int warps_total = (gridDim.x * blockDim.x) >> 5;

    for (int i = warp_global * 4 + oct; i < cnt; i += warps_total * 4) {
        float4 rec = __ldg(&g_rec[i]);   // broadcast within octet
        float tt = rec.x, cut = rec.y;
        int pk = __float_as_int(rec.z);
        int de = pk & 16383;
        int se = pk >> 14;

        // g[f] = sum_k T_k(tt) * W[k][f], then * cut
        float4 w = w4[0];
        float a0 = w.x, a1 = w.y, a2 = w.z, a3 = w.w;
        w = w4[8];
        a0 = fmaf(tt, w.x, a0); a1 = fmaf(tt, w.y, a1);
        a2 = fmaf(tt, w.z, a2); a3 = fmaf(tt, w.w, a3);
        float Tp = 1.0f, Tc = tt;
        float tt2 = 2.0f * tt;
#pragma unroll
        for (int kk = 2; kk < KDIM; kk++) {
            float Tn = fmaf(tt2, Tc, -Tp); Tp = Tc; Tc = Tn;
            w = w4[8 * kk];
            a0 = fmaf(Tn, w.x, a0); a1 = fmaf(Tn, w.y, a1);
            a2 = fmaf(Tn, w.z, a2); a3 = fmaf(Tn, w.w, a3);
        }
        a0 *= cut; a1 *= cut; a2 *= cut; a3 *= cut;

        float4 v;
        if (PASS == 1) {
            int ze = __float_as_int(rec.w);
            v = __ldg(reinterpret_cast<const float4*>(&emb[ze * FDIM + fg]));
            red4(&g_x0[de * FDIM + fg], a0 * v.x, a1 * v.y, a2 * v.z, a3 * v.w);
        } else {
            v = *reinterpret_cast<const float4*>(&g_x0[se * FDIM + fg]);
            red4(&g_y[de * FDIM + fg], a0 * v.x, a1 * v.y, a2 * v.z, a3 * v.w);
        }
    }
}

// Octet-per-atom MLP1 (4 atoms/warp, lane owns 4 features), grid-stride:
// x0 += (h * silu(h)) @ W2_0,  h = x0 @ W1_0.
__global__ void __launch_bounds__(256) mlp1_kernel(
    const float* __restrict__ W1, const float* __restrict__ W2, int N) {
    __shared__ float s1[FDIM * FDIM], s2[FDIM * FDIM];
    for (int i = threadIdx.x; i < FDIM * FDIM; i += blockDim.x) {
        s1[i] = W1[i]; s2[i] = W2[i];
    }
    __syncthreads();

    int lane = threadIdx.x & 31;
    int fg = (lane & 7) * 4;
    int obase = lane & 24;   // oct * 8
    int warp_global = (blockIdx.x * blockDim.x + threadIdx.x) >> 5;
    int warps_total = (gridDim.x * blockDim.x) >> 5;

    for (int n = warp_global * 4 + (lane >> 3); n < N; n += warps_total * 4) {
        float4 xv = *reinterpret_cast<const float4*>(&g_x0[n * FDIM + fg]);
        float x[4] = {xv.x, xv.y, xv.z, xv.w};

        float h[4] = {0.f, 0.f, 0.f, 0.f};
#pragma unroll
        for (int f = 0; f < FDIM; f++) {
            float xf = __shfl_sync(0xffffffffu, x[f & 3], obase | (f >> 2));
            float4 w = *reinterpret_cast<const float4*>(&s1[f * FDIM + fg]);
            h[0] = fmaf(xf, w.x, h[0]); h[1] = fmaf(xf, w.y, h[1]);
            h[2] = fmaf(xf, w.z, h[2]); h[3] = fmaf(xf, w.w, h[3]);
        }
        float t[4];
#pragma unroll
        for (int j = 0; j < 4; j++)
            t[j] = h[j] * h[j] / (1.0f + __expf(-h[j]));   // h*silu(h)

        float o[4] = {x[0], x[1], x[2], x[3]};
#pragma unroll
        for (int f = 0; f < FDIM; f++) {
            float tf = __shfl_sync(0xffffffffu, t[f & 3], obase | (f >> 2));
            float4 w = *reinterpret_cast<const float4*>(&s2[f * FDIM + fg]);
            o[0] = fmaf(tf, w.x, o[0]); o[1] = fmaf(tf, w.y, o[1]);
            o[2] = fmaf(tf, w.z, o[2]); o[3] = fmaf(tf, w.w, o[3]);
        }
        *reinterpret_cast<float4*>(&g_x0[n * FDIM + fg]) =
            make_float4(o[0], o[1], o[2], o[3]);
    }
}

// Octet-per-atom final, grid-stride: y2 = y + silu(y@W1_1)@W2_1 ;
// e = y2.w_out + b_out[Z] + epair; masked; atomic into out[batch].
__global__ void __launch_bounds__(256) final_kernel(
    const float* __restrict__ W1, const float* __restrict__ W2,
    const float* __restrict__ wout, const float* __restrict__ bout,
    const int* __restrict__ Z, const int* __restrict__ bseg,
    const float* __restrict__ amask, const float* __restrict__ bmask,
    float* __restrict__ out, int N) {
    __shared__ float s1[FDIM * FDIM], s2[FDIM * FDIM], sw[FDIM];
    for (int i = threadIdx.x; i < FDIM * FDIM; i += blockDim.x) {
        s1[i] = W1[i]; s2[i] = W2[i];
    }
    if (threadIdx.x < FDIM) sw[threadIdx.x] = wout[threadIdx.x];
    __syncthreads();

    int lane = threadIdx.x & 31;
    int fg = (lane & 7) * 4;
    int obase = lane & 24;
    int warp_global = (blockIdx.x * blockDim.x + threadIdx.x) >> 5;
    int warps_total = (gridDim.x * blockDim.x) >> 5;

    for (int n = warp_global * 4 + (lane >> 3); n < N; n += warps_total * 4) {
        float4 yv = *reinterpret_cast<const float4*>(&g_y[n * FDIM + fg]);
        float y[4] = {yv.x, yv.y, yv.z, yv.w};

        float h[4] = {0.f, 0.f, 0.f, 0.f};
#pragma unroll
        for (int f = 0; f < FDIM; f++) {
            float yf = __shfl_sync(0xffffffffu, y[f & 3], obase | (f >> 2));
            float4 w = *reinterpret_cast<const float4*>(&s1[f * FDIM + fg]);
            h[0] = fmaf(yf, w.x, h[0]); h[1] = fmaf(yf, w.y, h[1]);
            h[2] = fmaf(yf, w.z, h[2]); h[3] = fmaf(yf, w.w, h[3]);
        }
        float t[4];
#pragma unroll
        for (int j = 0; j < 4; j++)
            t[j] = h[j] / (1.0f + __expf(-h[j]));   // silu

        float o[4] = {y[0], y[1], y[2], y[3]};
#pragma unroll
        for (int f = 0; f < FDIM; f++) {
            float tf = __shfl_sync(0xffffffffu, t[f & 3], obase | (f >> 2));
            float4 w = *reinterpret_cast<const float4*>(&s2[f * FDIM + fg]);
            o[0] = fmaf(tf, w.x, o[0]); o[1] = fmaf(tf, w.y, o[1]);
            o[2] = fmaf(tf, w.z, o[2]); o[3] = fmaf(tf, w.w, o[3]);
        }

        // dot with w_out (4 channels per lane), reduce across the 8-lane octet
        float4 swv = *reinterpret_cast<const float4*>(&sw[fg]);
        float e = o[0] * swv.x + o[1] * swv.y + o[2] * swv.z + o[3] * swv.w;
        e += __shfl_xor_sync(0xffffffffu, e, 1);
        e += __shfl_xor_sync(0xffffffffu, e, 2);
        e += __shfl_xor_sync(0xffffffffu, e, 4);

        if ((lane & 7) == 0) {
            e += __ldg(&bout[__ldg(&Z[n])]) + g_epair[n];
            e *= __ldg(&amask[n]);
            int b = __ldg(&bseg[n]);
            atomicAdd(&out[b], e * __ldg(&bmask[b]));
        }
    }
}

extern "C" void kernel_launch(void* const* d_in, const int* in_sizes, int n_in,
                              void* d_out, int out_size) {
    const int*   Z     = (const int*)d_in[0];
    const float* pos   = (const float*)d_in[1];
    const int*   dst   = (const int*)d_in[2];
    const int*   src   = (const int*)d_in[3];
    const int*   bseg  = (const int*)d_in[4];
    // 'batch_size' may or may not be materialized as a size-1 input at index 5.
    int off = (in_sizes[5] == 1) ? 1 : 0;
    const float* bmask = (const float*)d_in[5 + off];
    const float* amask = (const float*)d_in[6 + off];
    const float* emb   = (const float*)d_in[7 + off];
    const float* Wr1_0 = (const float*)d_in[8 + off];
    const float* Wr2_0 = (const float*)d_in[9 + off];
    const float* W1_0  = (const float*)d_in[10 + off];
    const float* W2_0  = (const float*)d_in[11 + off];
    const float* Wr1_1 = (const float*)d_in[12 + off];
    const float* W1_1  = (const float*)d_in[13 + off];
    const float* W2_1  = (const float*)d_in[14 + off];
    const float* wout  = (const float*)d_in[15 + off];
    const float* bout  = (const float*)d_in[16 + off];

    int N = in_sizes[0];
    int E = in_sizes[2];
    int B = out_size;
    float* out = (float*)d_out;

    init_kernel<<<(N * FDIM / 4 + 255) / 256, 256>>>(out, B, Wr1_0, Wr2_0, pos, N);

    scalar_kernel<<<(E + 255) / 256, 256>>>(dst, src, Z, E);

    feat_kernel<1><<<512, 256>>>(emb, nullptr);

    // grid-stride: 256 blocks, each amortizes the weight prologue over 2 passes
    mlp1_kernel<<<256, 256>>>(W1_0, W2_0, N);

    feat_kernel<2><<<512, 256>>>(emb, Wr1_1);

    final_kernel<<<256, 256>>>(W1_1, W2_1, wout, bout, Z, bseg,
                               amask, bmask, out, N);
}

// round 15
// speedup vs baseline: 1.0635x; 1.0635x over previous
#include <cuda_runtime.h>
#include <cuda_bf16.h>

#define NMAX 16384
#define FDIM 32
#define KDIM 16
#define EMAX 262144

// Scratch (no allocations allowed) — sizes fixed by the problem setup.
__device__ __align__(16) float g_x0[NMAX * FDIM];
__device__ __align__(16) float g_y[NMAX * FDIM];
__device__ float g_epair[NMAX];
__device__ __align__(16) float g_Wc[KDIM * FDIM];
__device__ __align__(16) float4 g_rec[EMAX];   // compacted edges: (tt, cut, d|s<<14, z)
__device__ __align__(16) float4 g_pos4[NMAX];  // packed positions
__device__ float g_z23[32];                    // z^0.23 LUT
__device__ int g_cnt;

__device__ __forceinline__ void red4(float* addr, float a, float b, float c, float d) {
    atomicAdd(reinterpret_cast<float4*>(addr), make_float4(a, b, c, d));
}

// Zero accumulators + output + counter; build Wc + z^0.23 LUT; pack positions.
__global__ void init_kernel(float* __restrict__ out, int B,
                            const float* __restrict__ Wr10,
                            const float* __restrict__ Wr20,
                            const float* __restrict__ pos, int N) {
    int i = blockIdx.x * blockDim.x + threadIdx.x;
    int tot4 = N * FDIM / 4;
    float4 z4 = make_float4(0.f, 0.f, 0.f, 0.f);
    if (i < tot4) {
        reinterpret_cast<float4*>(g_x0)[i] = z4;
        reinterpret_cast<float4*>(g_y)[i] = z4;
    }
    if (i < N) {
        g_epair[i] = 0.0f;
        g_pos4[i] = make_float4(pos[3 * i], pos[3 * i + 1], pos[3 * i + 2], 0.0f);
    }
    if (i < B) out[i] = 0.0f;
    if (i < KDIM * FDIM) g_Wc[i] = 0.282095f * Wr10[i] + Wr20[i];
    if (i < 32) g_z23[i] = powf((float)i, 0.23f);
    if (i == 0) g_cnt = 0;
}

// Scalar pass: one edge per lane. Distance, cutoff, tt, ZBL pair energy.
// Valid edges compacted into g_rec (block-aggregated atomic: 1 global RED/block).
__global__ void __launch_bounds__(256) scalar_kernel(
    const int*   __restrict__ dst,
    const int*   __restrict__ src,
    const int*   __restrict__ Z,
    int E) {
    __shared__ int sWarpCnt[8];
    __shared__ int sWarpOff[8];
    __shared__ int sBlockBase;

    int e = blockIdx.x * blockDim.x + threadIdx.x;
    int lane = threadIdx.x & 31;
    int wid = threadIdx.x >> 5;

    bool valid = false;
    float4 rec;
    if (e < E) {
        int d = __ldg(&dst[e]);
        int s = __ldg(&src[e]);
        float4 ps = __ldg(&g_pos4[s]);
        float4 pd = __ldg(&g_pos4[d]);
        float dx = ps.x - pd.x;
        float dy = ps.y - pd.y;
        float dz = ps.z - pd.z;
        float r = sqrtf(dx * dx + dy * dy + dz * dz + 1e-10f);
        r = fmaxf(r, 1e-4f);
        if (r < 6.0f) {
            valid = true;
            float u = r * (1.0f / 6.0f);
            float cut = __expf(-__fdividef(u * u, 1.0f - u * u));
            float tt = 2.0f * __expf(-r) - 1.0f;
            tt = fminf(fmaxf(tt, -1.0f), 1.0f);

            int zs = __ldg(&Z[s]);
            int zd = __ldg(&Z[d]);
            float zdf = (float)zd;
            float zsf = (float)zs;
            // ra = r/aa, aa = 0.46853332/(z23d+z23s+eps)  ->  pure multiplies
            float ra = r * (__ldg(&g_z23[zd]) + __ldg(&g_z23[zs]) + 1e-10f)
                         * (1.0f / 0.46853332f);
            float phi = 0.18175f * __expf(-3.1998f  * ra)
                      + 0.50986f * __expf(-0.94229f * ra)
                      + 0.28022f * __expf(-0.4029f  * ra)
                      + 0.02817f * __expf(-0.20162f * ra);
            float ep = 0.5f * 14.399645f * zdf * zsf * __fdividef(phi * cut, r);
            atomicAdd(&g_epair[d], ep);

            rec = make_float4(tt, cut,
                              __int_as_float(d | (s << 14)),
                              __int_as_float(zs));
        }
    }

    unsigned mask = __ballot_sync(0xffffffffu, valid);
    int wcnt = __popc(mask);
    if (lane == 0) sWarpCnt[wid] = wcnt;
    __syncthreads();
    if (threadIdx.x == 0) {
        int tot = 0;
#pragma unroll
        for (int w = 0; w < 8; w++) { sWarpOff[w] = tot; tot += sWarpCnt[w]; }
        sBlockBase = atomicAdd(&g_cnt, tot);
    }
    __syncthreads();
    if (valid) {
        int rank = __popc(mask & ((1u << lane) - 1u));
        g_rec[sBlockBase + sWarpOff[wid] + rank] = rec;
    }
}

// Feature pass over the compacted edge list. One octet of lanes per edge
// (4 channels/lane), 4 edges per warp-iteration, grid-stride over g_cnt.
// PASS=1: g_x0 += (rad@Wc)    * emb[Z[src]]
// PASS=2: g_y  += (rad@Wr1_1) * g_x0[src]
template <int PASS>
__global__ void __launch_bounds__(256) feat_kernel(
    const float* __restrict__ emb,    // PASS=1
    const float* __restrict__ Wext) { // Wr1_1 for PASS=2
    __shared__ float sW[KDIM * FDIM];
    if (PASS == 1) {
        for (int i = threadIdx.x; i < KDIM * FDIM; i += blockDim.x) sW[i] = g_Wc[i];
    } else {
        for (int i = threadIdx.x; i < KDIM * FDIM; i += blockDim.x) sW[i] = Wext[i];
    }
    __syncthreads();

    int cnt = g_cnt;
    int lane = threadIdx.x & 31;
    int oct = lane >> 3;
    int fg = (lane & 7) * 4;
    const float4* w4 = reinterpret_cast<const float4*>(&sW[fg]);  // row stride: 8 float4

    int warp_global = (blockIdx.x * blockDim.x + threadIdx.x) >> 5;
    int warps_total = (gridDim.x * blockDim.x) >> 5;

    for (int i = warp_global * 4 + oct; i < cnt; i += warps_total * 4) {
        float4 rec = __ldg(&g_rec[i]);   // broadcast within octet
        float tt = rec.x, cut = rec.y;
        int pk = __float_as_int(rec.z);
        int de = pk & 16383;
        int se = pk >> 14;

        // g[f] = sum_k T_k(tt) * W[k][f], then * cut
        float4 w = w4[0];
        float a0 = w.x, a1 = w.y, a2 = w.z, a3 = w.w;
        w = w4[8];
        a0 = fmaf(tt, w.x, a0); a1 = fmaf(tt, w.y, a1);
        a2 = fmaf(tt, w.z, a2); a3 = fmaf(tt, w.w, a3);
        float Tp = 1.0f, Tc = tt;
        float tt2 = 2.0f * tt;
#pragma unroll
        for (int kk = 2; kk < KDIM; kk++) {
            float Tn = fmaf(tt2, Tc, -Tp); Tp = Tc; Tc = Tn;
            w = w4[8 * kk];
            a0 = fmaf(Tn, w.x, a0); a1 = fmaf(Tn, w.y, a1);
            a2 = fmaf(Tn, w.z, a2); a3 = fmaf(Tn, w.w, a3);
        }
        a0 *= cut; a1 *= cut; a2 *= cut; a3 *= cut;

        float4 v;
        if (PASS == 1) {
            int ze = __float_as_int(rec.w);
            v = __ldg(reinterpret_cast<const float4*>(&emb[ze * FDIM + fg]));
            red4(&g_x0[de * FDIM + fg], a0 * v.x, a1 * v.y, a2 * v.z, a3 * v.w);
        } else {
            v = *reinterpret_cast<const float4*>(&g_x0[se * FDIM + fg]);
            red4(&g_y[de * FDIM + fg], a0 * v.x, a1 * v.y, a2 * v.z, a3 * v.w);
        }
    }
}

// Octet-per-atom MLP1 (4 atoms/warp, lane owns 4 features):
// x0 += (h * silu(h)) @ W2_0,  h = x0 @ W1_0.
__global__ void __launch_bounds__(256) mlp1_kernel(
    const float* __restrict__ W1, const float* __restrict__ W2, int N) {
    __shared__ float s1[FDIM * FDIM], s2[FDIM * FDIM];
    for (int i = threadIdx.x; i < FDIM * FDIM; i += blockDim.x) {
        s1[i] = W1[i]; s2[i] = W2[i];
    }
    __syncthreads();

    int lane = threadIdx.x & 31;
    int fg = (lane & 7) * 4;
    int obase = lane & 24;   // oct * 8
    int n = ((blockIdx.x * blockDim.x + threadIdx.x) >> 5) * 4 + (lane >> 3);
    if (n >= N) return;

    float4 xv = *reinterpret_cast<const float4*>(&g_x0[n * FDIM + fg]);
    float x[4] = {xv.x, xv.y, xv.z, xv.w};

    float h[4] = {0.f, 0.f, 0.f, 0.f};
#pragma unroll
    for (int f = 0; f < FDIM; f++) {
        float xf = __shfl_sync(0xffffffffu, x[f & 3], obase | (f >> 2));
        float4 w = *reinterpret_cast<const float4*>(&s1[f * FDIM + fg]);
        h[0] = fmaf(xf, w.x, h[0]); h[1] = fmaf(xf, w.y, h[1]);
        h[2] = fmaf(xf, w.z, h[2]); h[3] = fmaf(xf, w.w, h[3]);
    }
    float t[4];
#pragma unroll
    for (int j = 0; j < 4; j++)
        t[j] = __fdividef(h[j] * h[j], 1.0f + __expf(-h[j]));   // h*silu(h)

    float o[4] = {x[0], x[1], x[2], x[3]};
#pragma unroll
    for (int f = 0; f < FDIM; f++) {
        float tf = __shfl_sync(0xffffffffu, t[f & 3], obase | (f >> 2));
        float4 w = *reinterpret_cast<const float4*>(&s2[f * FDIM + fg]);
        o[0] = fmaf(tf, w.x, o[0]); o[1] = fmaf(tf, w.y, o[1]);
        o[2] = fmaf(tf, w.z, o[2]); o[3] = fmaf(tf, w.w, o[3]);
    }
    *reinterpret_cast<float4*>(&g_x0[n * FDIM + fg]) =
        make_float4(o[0], o[1], o[2], o[3]);
}

// Octet-per-atom final: y2 = y + silu(y@W1_1)@W2_1 ;
// e = y2.w_out + b_out[Z] + epair; masked; atomic into out[batch].
__global__ void __launch_bounds__(256) final_kernel(
    const float* __restrict__ W1, const float* __restrict__ W2,
    const float* __restrict__ wout, const float* __restrict__ bout,
    const int* __restrict__ Z, const int* __restrict__ bseg,
    const float* __restrict__ amask, const float* __restrict__ bmask,
    float* __restrict__ out, int N) {
    __shared__ float s1[FDIM * FDIM], s2[FDIM * FDIM], sw[FDIM];
    for (int i = threadIdx.x; i < FDIM * FDIM; i += blockDim.x) {
        s1[i] = W1[i]; s2[i] = W2[i];
    }
    if (threadIdx.x < FDIM) sw[threadIdx.x] = wout[threadIdx.x];
    __syncthreads();

    int lane = threadIdx.x & 31;
    int fg = (lane & 7) * 4;
    int obase = lane & 24;
    int n = ((blockIdx.x * blockDim.x + threadIdx.x) >> 5) * 4 + (lane >> 3);
    if (n >= N) return;

    float4 yv = *reinterpret_cast<const float4*>(&g_y[n * FDIM + fg]);
    float y[4] = {yv.x, yv.y, yv.z, yv.w};

    float h[4] = {0.f, 0.f, 0.f, 0.f};
#pragma unroll
    for (int f = 0; f < FDIM; f++) {
        float yf = __shfl_sync(0xffffffffu, y[f & 3], obase | (f >> 2));
        float4 w = *reinterpret_cast<const float4*>(&s1[f * FDIM + fg]);
        h[0] = fmaf(yf, w.x, h[0]); h[1] = fmaf(yf, w.y, h[1]);
        h[2] = fmaf(yf, w.z, h[2]); h[3] = fmaf(yf, w.w, h[3]);
    }
    float t[4];
#pragma unroll
    for (int j = 0; j < 4; j++)
        t[j] = __fdividef(h[j], 1.0f + __expf(-h[j]));   // silu

    float o[4] = {y[0], y[1], y[2], y[3]};
#pragma unroll
    for (int f = 0; f < FDIM; f++) {
        float tf = __shfl_sync(0xffffffffu, t[f & 3], obase | (f >> 2));
        float4 w = *reinterpret_cast<const float4*>(&s2[f * FDIM + fg]);
        o[0] = fmaf(tf, w.x, o[0]); o[1] = fmaf(tf, w.y, o[1]);
        o[2] = fmaf(tf, w.z, o[2]); o[3] = fmaf(tf, w.w, o[3]);
    }

    // dot with w_out (4 channels per lane), reduce across the 8-lane octet
    float4 swv = *reinterpret_cast<const float4*>(&sw[fg]);
    float e = o[0] * swv.x + o[1] * swv.y + o[2] * swv.z + o[3] * swv.w;
    e += __shfl_xor_sync(0xffffffffu, e, 1);
    e += __shfl_xor_sync(0xffffffffu, e, 2);
    e += __shfl_xor_sync(0xffffffffu, e, 4);

    if ((lane & 7) == 0) {
        e += __ldg(&bout[__ldg(&Z[n])]) + g_epair[n];
        e *= __ldg(&amask[n]);
        int b = __ldg(&bseg[n]);
        atomicAdd(&out[b], e * __ldg(&bmask[b]));
    }
}

extern "C" void kernel_launch(void* const* d_in, const int* in_sizes, int n_in,
                              void* d_out, int out_size) {
    const int*   Z     = (const int*)d_in[0];
    const float* pos   = (const float*)d_in[1];
    const int*   dst   = (const int*)d_in[2];
    const int*   src   = (const int*)d_in[3];
    const int*   bseg  = (const int*)d_in[4];
    // 'batch_size' may or may not be materialized as a size-1 input at index 5.
    int off = (in_sizes[5] == 1) ? 1 : 0;
    const float* bmask = (const float*)d_in[5 + off];
    const float* amask = (const float*)d_in[6 + off];
    const float* emb   = (const float*)d_in[7 + off];
    const float* Wr1_0 = (const float*)d_in[8 + off];
    const float* Wr2_0 = (const float*)d_in[9 + off];
    const float* W1_0  = (const float*)d_in[10 + off];
    const float* W2_0  = (const float*)d_in[11 + off];
    const float* Wr1_1 = (const float*)d_in[12 + off];
    const float* W1_1  = (const float*)d_in[13 + off];
    const float* W2_1  = (const float*)d_in[14 + off];
    const float* wout  = (const float*)d_in[15 + off];
    const float* bout  = (const float*)d_in[16 + off];

    int N = in_sizes[0];
    int E = in_sizes[2];
    int B = out_size;
    float* out = (float*)d_out;

    init_kernel<<<(N * FDIM / 4 + 255) / 256, 256>>>(out, B, Wr1_0, Wr2_0, pos, N);

    scalar_kernel<<<(E + 255) / 256, 256>>>(dst, src, Z, E);

    feat_kernel<1><<<1024, 256>>>(emb, nullptr);

    // 4 atoms per warp -> 32 atoms per 256-thread block
    mlp1_kernel<<<(N + 31) / 32, 256>>>(W1_0, W2_0, N);

    feat_kernel<2><<<1024, 256>>>(emb, Wr1_1);

    final_kernel<<<(N + 31) / 32, 256>>>(W1_1, W2_1, wout, bout, Z, bseg,
                                         amask, bmask, out, N);
}

// round 16
// speedup vs baseline: 1.0703x; 1.0063x over previous
#include <cuda_runtime.h>
#include <cuda_bf16.h>

#define NMAX 16384
#define FDIM 32
#define KDIM 16
#define EMAX 262144

// Scratch (no allocations allowed) — sizes fixed by the problem setup.
__device__ __align__(16) float g_x0[NMAX * FDIM];
__device__ __align__(16) float g_y[NMAX * FDIM];
__device__ float g_epair[NMAX];
__device__ __align__(16) float g_Wc[KDIM * FDIM];
__device__ __align__(16) float4 g_rec[EMAX];   // compacted edges: (tt, cut, d|s<<14, z)
__device__ __align__(16) float4 g_pos4[NMAX];  // packed positions
__device__ float g_z23[32];                    // z^0.23 LUT
__device__ int g_cnt;

__device__ __forceinline__ void red4(float* addr, float a, float b, float c, float d) {
    atomicAdd(reinterpret_cast<float4*>(addr), make_float4(a, b, c, d));
}

// Zero accumulators + output + counter; build Wc + z^0.23 LUT; pack positions.
__global__ void init_kernel(float* __restrict__ out, int B,
                            const float* __restrict__ Wr10,
                            const float* __restrict__ Wr20,
                            const float* __restrict__ pos, int N) {
    int i = blockIdx.x * blockDim.x + threadIdx.x;
    int tot4 = N * FDIM / 4;
    float4 z4 = make_float4(0.f, 0.f, 0.f, 0.f);
    if (i < tot4) {
        reinterpret_cast<float4*>(g_x0)[i] = z4;
        reinterpret_cast<float4*>(g_y)[i] = z4;
    }
    if (i < N) {
        g_epair[i] = 0.0f;
        g_pos4[i] = make_float4(pos[3 * i], pos[3 * i + 1], pos[3 * i + 2], 0.0f);
    }
    if (i < B) out[i] = 0.0f;
    if (i < KDIM * FDIM) g_Wc[i] = 0.282095f * Wr10[i] + Wr20[i];
    if (i < 32) g_z23[i] = powf((float)i, 0.23f);
    if (i == 0) g_cnt = 0;
}

// Scalar pass: one edge per lane. Distance, cutoff, tt, ZBL pair energy.
// Valid edges compacted into g_rec (block-aggregated atomic: 1 global RED/block).
__global__ void __launch_bounds__(256) scalar_kernel(
    const int*   __restrict__ dst,
    const int*   __restrict__ src,
    const int*   __restrict__ Z,
    int E) {
    __shared__ int sWarpCnt[8];
    __shared__ int sWarpOff[8];
    __shared__ int sBlockBase;

    int e = blockIdx.x * blockDim.x + threadIdx.x;
    int lane = threadIdx.x & 31;
    int wid = threadIdx.x >> 5;

    bool valid = false;
    float4 rec;
    if (e < E) {
        int d = __ldg(&dst[e]);
        int s = __ldg(&src[e]);
        float4 ps = __ldg(&g_pos4[s]);
        float4 pd = __ldg(&g_pos4[d]);
        float dx = ps.x - pd.x;
        float dy = ps.y - pd.y;
        float dz = ps.z - pd.z;
        float r = sqrtf(dx * dx + dy * dy + dz * dz + 1e-10f);
        r = fmaxf(r, 1e-4f);
        if (r < 6.0f) {
            valid = true;
            float u = r * (1.0f / 6.0f);
            float cut = __expf(-__fdividef(u * u, 1.0f - u * u));
            float tt = 2.0f * __expf(-r) - 1.0f;
            tt = fminf(fmaxf(tt, -1.0f), 1.0f);

            int zs = __ldg(&Z[s]);
            int zd = __ldg(&Z[d]);
            float zdf = (float)zd;
            float zsf = (float)zs;
            // ra = r/aa, aa = 0.46853332/(z23d+z23s+eps)  ->  pure multiplies
            float ra = r * (__ldg(&g_z23[zd]) + __ldg(&g_z23[zs]) + 1e-10f)
                         * (1.0f / 0.46853332f);
            float phi = 0.18175f * __expf(-3.1998f  * ra)
                      + 0.50986f * __expf(-0.94229f * ra)
                      + 0.28022f * __expf(-0.4029f  * ra)
                      + 0.02817f * __expf(-0.20162f * ra);
            float ep = 0.5f * 14.399645f * zdf * zsf * __fdividef(phi * cut, r);
            atomicAdd(&g_epair[d], ep);

            rec = make_float4(tt, cut,
                              __int_as_float(d | (s << 14)),
                              __int_as_float(zs));
        }
    }

    unsigned mask = __ballot_sync(0xffffffffu, valid);
    int wcnt = __popc(mask);
    if (lane == 0) sWarpCnt[wid] = wcnt;
    __syncthreads();
    if (threadIdx.x == 0) {
        int tot = 0;
#pragma unroll
        for (int w = 0; w < 8; w++) { sWarpOff[w] = tot; tot += sWarpCnt[w]; }
        sBlockBase = atomicAdd(&g_cnt, tot);
    }
    __syncthreads();
    if (valid) {
        int rank = __popc(mask & ((1u << lane) - 1u));
        g_rec[sBlockBase + sWarpOff[wid] + rank] = rec;
    }
}

// Feature pass over the compacted edge list. One octet of lanes per edge
// (4 channels/lane), 4 edges per warp-iteration, grid-stride over g_cnt.
// PASS=1: g_x0 += (rad@Wc)    * emb[Z[src]]
// PASS=2: g_y  += (rad@Wr1_1) * g_x0[src]
template <int PASS>
__global__ void __launch_bounds__(256) feat_kernel(
    const float* __restrict__ emb,    // PASS=1
    const float* __restrict__ Wext) { // Wr1_1 for PASS=2
    __shared__ float sW[KDIM * FDIM];
    if (PASS == 1) {
        for (int i = threadIdx.x; i < KDIM * FDIM; i += blockDim.x) sW[i] = g_Wc[i];
    } else {
        for (int i = threadIdx.x; i < KDIM * FDIM; i += blockDim.x) sW[i] = Wext[i];
    }
    __syncthreads();

    int cnt = g_cnt;
    int lane = threadIdx.x & 31;
    int oct = lane >> 3;
    int fg = (lane & 7) * 4;
    const float4* w4 = reinterpret_cast<const float4*>(&sW[fg]);  // row stride: 8 float4

    int warp_global = (blockIdx.x * blockDim.x + threadIdx.x) >> 5;
    int warps_total = (gridDim.x * blockDim.x) >> 5;

    for (int i = warp_global * 4 + oct; i < cnt; i += warps_total * 4) {
        float4 rec = __ldg(&g_rec[i]);   // broadcast within octet
        float tt = rec.x, cut = rec.y;
        int pk = __float_as_int(rec.z);
        int de = pk & 16383;
        int se = pk >> 14;

        // g[f] = sum_k T_k(tt) * W[k][f], then * cut
        float4 w = w4[0];
        float a0 = w.x, a1 = w.y, a2 = w.z, a3 = w.w;
        w = w4[8];
        a0 = fmaf(tt, w.x, a0); a1 = fmaf(tt, w.y, a1);
        a2 = fmaf(tt, w.z, a2); a3 = fmaf(tt, w.w, a3);
        float Tp = 1.0f, Tc = tt;
        float tt2 = 2.0f * tt;
#pragma unroll
        for (int kk = 2; kk < KDIM; kk++) {
            float Tn = fmaf(tt2, Tc, -Tp); Tp = Tc; Tc = Tn;
            w = w4[8 * kk];
            a0 = fmaf(Tn, w.x, a0); a1 = fmaf(Tn, w.y, a1);
            a2 = fmaf(Tn, w.z, a2); a3 = fmaf(Tn, w.w, a3);
        }
        a0 *= cut; a1 *= cut; a2 *= cut; a3 *= cut;

        float4 v;
        if (PASS == 1) {
            int ze = __float_as_int(rec.w);
            v = __ldg(reinterpret_cast<const float4*>(&emb[ze * FDIM + fg]));
            red4(&g_x0[de * FDIM + fg], a0 * v.x, a1 * v.y, a2 * v.z, a3 * v.w);
        } else {
            v = *reinterpret_cast<const float4*>(&g_x0[se * FDIM + fg]);
            red4(&g_y[de * FDIM + fg], a0 * v.x, a1 * v.y, a2 * v.z, a3 * v.w);
        }
    }
}

// 2 atoms/warp MLP1 (16 lanes per atom, lane owns 2 features):
// x0 += (h * silu(h)) @ W2_0,  h = x0 @ W1_0.
__global__ void __launch_bounds__(256) mlp1_kernel(
    const float* __restrict__ W1, const float* __restrict__ W2, int N) {
    __shared__ float s1[FDIM * FDIM], s2[FDIM * FDIM];
    for (int i = threadIdx.x; i < FDIM * FDIM; i += blockDim.x) {
        s1[i] = W1[i]; s2[i] = W2[i];
    }
    __syncthreads();

    int lane = threadIdx.x & 31;
    int fg = (lane & 15) * 2;
    int abase = lane & 16;   // lane-group base of this atom's 16 lanes
    int n = ((blockIdx.x * blockDim.x + threadIdx.x) >> 5) * 2 + (lane >> 4);
    if (n >= N) return;

    float2 xv = *reinterpret_cast<const float2*>(&g_x0[n * FDIM + fg]);
    float x[2] = {xv.x, xv.y};

    float h[2] = {0.f, 0.f};
#pragma unroll
    for (int f = 0; f < FDIM; f++) {
        float xf = __shfl_sync(0xffffffffu, x[f & 1], abase | (f >> 1));
        float2 w = *reinterpret_cast<const float2*>(&s1[f * FDIM + fg]);
        h[0] = fmaf(xf, w.x, h[0]);
        h[1] = fmaf(xf, w.y, h[1]);
    }
    float t[2];
    t[0] = __fdividef(h[0] * h[0], 1.0f + __expf(-h[0]));   // h*silu(h)
    t[1] = __fdividef(h[1] * h[1], 1.0f + __expf(-h[1]));

    float o[2] = {x[0], x[1]};
#pragma unroll
    for (int f = 0; f < FDIM; f++) {
        float tf = __shfl_sync(0xffffffffu, t[f & 1], abase | (f >> 1));
        float2 w = *reinterpret_cast<const float2*>(&s2[f * FDIM + fg]);
        o[0] = fmaf(tf, w.x, o[0]);
        o[1] = fmaf(tf, w.y, o[1]);
    }
    *reinterpret_cast<float2*>(&g_x0[n * FDIM + fg]) = make_float2(o[0], o[1]);
}

// 2 atoms/warp final: y2 = y + silu(y@W1_1)@W2_1 ;
// e = y2.w_out + b_out[Z] + epair; masked; atomic into out[batch].
__global__ void __launch_bounds__(256) final_kernel(
    const float* __restrict__ W1, const float* __restrict__ W2,
    const float* __restrict__ wout, const float* __restrict__ bout,
    const int* __restrict__ Z, const int* __restrict__ bseg,
    const float* __restrict__ amask, const float* __restrict__ bmask,
    float* __restrict__ out, int N) {
    __shared__ float s1[FDIM * FDIM], s2[FDIM * FDIM], sw[FDIM];
    for (int i = threadIdx.x; i < FDIM * FDIM; i += blockDim.x) {
        s1[i] = W1[i]; s2[i] = W2[i];
    }
    if (threadIdx.x < FDIM) sw[threadIdx.x] = wout[threadIdx.x];
    __syncthreads();

    int lane = threadIdx.x & 31;
    int fg = (lane & 15) * 2;
    int abase = lane & 16;
    int n = ((blockIdx.x * blockDim.x + threadIdx.x) >> 5) * 2 + (lane >> 4);
    if (n >= N) return;

    float2 yv = *reinterpret_cast<const float2*>(&g_y[n * FDIM + fg]);
    float y[2] = {yv.x, yv.y};

    float h[2] = {0.f, 0.f};
#pragma unroll
    for (int f = 0; f < FDIM; f++) {
        float yf = __shfl_sync(0xffffffffu, y[f & 1], abase | (f >> 1));
        float2 w = *reinterpret_cast<const float2*>(&s1[f * FDIM + fg]);
        h[0] = fmaf(yf, w.x, h[0]);
        h[1] = fmaf(yf, w.y, h[1]);
    }
    float t[2];
    t[0] = __fdividef(h[0], 1.0f + __expf(-h[0]));   // silu
    t[1] = __fdividef(h[1], 1.0f + __expf(-h[1]));

    float o[2] = {y[0], y[1]};
#pragma unroll
    for (int f = 0; f < FDIM; f++) {
        float tf = __shfl_sync(0xffffffffu, t[f & 1], abase | (f >> 1));
        float2 w = *reinterpret_cast<const float2*>(&s2[f * FDIM + fg]);
        o[0] = fmaf(tf, w.x, o[0]);
        o[1] = fmaf(tf, w.y, o[1]);
    }

    // dot with w_out (2 channels per lane), reduce across the 16-lane group
    float2 swv = *reinterpret_cast<const float2*>(&sw[fg]);
    float e = o[0] * swv.x + o[1] * swv.y;
    e += __shfl_xor_sync(0xffffffffu, e, 1);
    e += __shfl_xor_sync(0xffffffffu, e, 2);
    e += __shfl_xor_sync(0xffffffffu, e, 4);
    e += __shfl_xor_sync(0xffffffffu, e, 8);

    if ((lane & 15) == 0) {
        e += __ldg(&bout[__ldg(&Z[n])]) + g_epair[n];
        e *= __ldg(&amask[n]);
        int b = __ldg(&bseg[n]);
        atomicAdd(&out[b], e * __ldg(&bmask[b]));
    }
}

extern "C" void kernel_launch(void* const* d_in, const int* in_sizes, int n_in,
                              void* d_out, int out_size) {
    const int*   Z     = (const int*)d_in[0];
    const float* pos   = (const float*)d_in[1];
    const int*   dst   = (const int*)d_in[2];
    const int*   src   = (const int*)d_in[3];
    const int*   bseg  = (const int*)d_in[4];
    // 'batch_size' may or may not be materialized as a size-1 input at index 5.
    int off = (in_sizes[5] == 1) ? 1 : 0;
    const float* bmask = (const float*)d_in[5 + off];
    const float* amask = (const float*)d_in[6 + off];
    const float* emb   = (const float*)d_in[7 + off];
    const float* Wr1_0 = (const float*)d_in[8 + off];
    const float* Wr2_0 = (const float*)d_in[9 + off];
    const float* W1_0  = (const float*)d_in[10 + off];
    const float* W2_0  = (const float*)d_in[11 + off];
    const float* Wr1_1 = (const float*)d_in[12 + off];
    const float* W1_1  = (const float*)d_in[13 + off];
    const float* W2_1  = (const float*)d_in[14 + off];
    const float* wout  = (const float*)d_in[15 + off];
    const float* bout  = (const float*)d_in[16 + off];

    int N = in_sizes[0];
    int E = in_sizes[2];
    int B = out_size;
    float* out = (float*)d_out;

    init_kernel<<<(N * FDIM / 4 + 255) / 256, 256>>>(out, B, Wr1_0, Wr2_0, pos, N);

    scalar_kernel<<<(E + 255) / 256, 256>>>(dst, src, Z, E);

    feat_kernel<1><<<1024, 256>>>(emb, nullptr);

    // 2 atoms per warp -> 16 atoms per 256-thread block
    mlp1_kernel<<<(N + 15) / 16, 256>>>(W1_0, W2_0, N);

    feat_kernel<2><<<1024, 256>>>(emb, Wr1_1);

    final_kernel<<<(N + 15) / 16, 256>>>(W1_1, W2_1, wout, bout, Z, bseg,
                                         amask, bmask, out, N);
}